// round 1
// baseline (speedup 1.0000x reference)
#include <cuda_runtime.h>

// e3LayerNorm: segment (graph) layernorm over irreps 128x0e + 64x1o + 32x2e.
// x: [N, 480] fp32, weight: [224], bias: [128], batch: [N] sorted graph ids in [0,64).
// out[i, c] = a[g, c] * x[i, c] + b[g, c]  where a/b fold mean-subtract, inv-std
// (scalar cols only), weight scale, and bias.
//
// Strategy: batch is sorted -> graphs contiguous. Process 8 groups of 8 graphs
// (~48MB input/group) with alternating stats/normalize launches so the second
// read of each group hits L2 (126 MB). Output stored with .cs (evict-first).

#define NTOT   480
#define NSCAL  128
#define NB     64
#define GSZ    8
#define NGROUPS (NB / GSZ)
#define THREADS 512
#define GRID_MAIN 512
#define EPSV   1e-5f
#define MAXN   200000

__device__ int   g_start[NB + 1];
__device__ int   g_batch[MAXN];
__device__ float g_sum[NB][NTOT];
__device__ float g_sumsq[NB][NSCAL];

// Zero accumulators + convert batch (int64 or int32) to int32 scratch.
__global__ void prep_kernel(const void* __restrict__ batch_raw, int N) {
    int i = blockIdx.x * blockDim.x + threadIdx.x;
    if (i < NB * NTOT)  ((float*)g_sum)[i]   = 0.f;
    if (i < NB * NSCAL) ((float*)g_sumsq)[i] = 0.f;
    if (i < N && i < MAXN) {
        const int* b32 = (const int*)batch_raw;
        // Probe an ODD int32 index near the end: if the buffer is int64, that
        // word is a high word (== 0); if int32, it's the last sorted graph id
        // (~63). Threshold at 32.
        int probe = (N & 1) ? (N - 2) : (N - 1);
        bool is64 = (b32[probe] < 32);
        g_batch[i] = is64 ? (int)(((const long long*)batch_raw)[i]) : b32[i];
    }
}

// g_start[g] = lower_bound(batch, g); g_start[NB] = N. Handles empty graphs.
__global__ void bounds_kernel(int N) {
    int t = threadIdx.x;
    if (t > NB) return;
    int lo = 0, hi = N;
    while (lo < hi) {
        int mid = (lo + hi) >> 1;
        if (g_batch[mid] < t) lo = mid + 1; else hi = mid;
    }
    g_start[t] = lo;
}

// Per-group stats: column sums (all 480 cols) + sum of squares (cols < 128).
// Thread t owns column t; rows of the group are split evenly across CTAs.
// Register accumulation per contiguous graph run; atomicAdd flush on boundary.
__global__ __launch_bounds__(THREADS) void stats_kernel(
    const float* __restrict__ x, int group)
{
    int g0 = group * GSZ;
    int s0 = g_start[g0], s1 = g_start[g0 + GSZ];
    long long len = (long long)(s1 - s0);
    int r0 = s0 + (int)(len * blockIdx.x / gridDim.x);
    int r1 = s0 + (int)(len * (blockIdx.x + 1) / gridDim.x);
    int t = threadIdx.x;
    if (t >= NTOT) return;   // no __syncthreads in this kernel

    float acc = 0.f, accsq = 0.f;
    int cur = -1;
    for (int r = r0; r < r1; ++r) {
        int g = g_batch[r];
        if (g != cur) {
            if (cur >= 0) {
                atomicAdd(&g_sum[cur][t], acc);
                if (t < NSCAL) atomicAdd(&g_sumsq[cur][t], accsq);
            }
            acc = 0.f; accsq = 0.f; cur = g;
        }
        float v = x[r * NTOT + t];
        acc += v;
        accsq += v * v;
    }
    if (cur >= 0) {
        atomicAdd(&g_sum[cur][t], acc);
        if (t < NSCAL) atomicAdd(&g_sumsq[cur][t], accsq);
    }
}

// Per-group normalize: out = a*x + b. a/b computed per graph transition
// (uniform across the block since rows are looped uniformly).
__global__ __launch_bounds__(THREADS) void norm_kernel(
    const float* __restrict__ x,
    const float* __restrict__ weight,
    const float* __restrict__ bias,
    float* __restrict__ out, int group)
{
    __shared__ float sred[NSCAL];
    __shared__ float snorm;

    int g0 = group * GSZ;
    int s0 = g_start[g0], s1 = g_start[g0 + GSZ];
    long long len = (long long)(s1 - s0);
    int r0 = s0 + (int)(len * blockIdx.x / gridDim.x);
    int r1 = s0 + (int)(len * (blockIdx.x + 1) / gridDim.x);
    int t = threadIdx.x;
    bool active = (t < NTOT);

    // column -> weight channel: 0..127 scalar(d=1), 128..319 d=3, 320..479 d=5
    int ch = (t < NSCAL) ? t : (t < 320 ? 128 + (t - 128) / 3
                                        : 192 + (t - 320) / 5);
    float w = 0.f, bi = 0.f;
    if (active) {
        w = weight[ch];
        if (t < NSCAL) bi = bias[t];
    }

    float a = 0.f, b = 0.f;
    int cur = -1;
    for (int r = r0; r < r1; ++r) {
        int g = g_batch[r];
        if (g != cur) {                       // uniform across block
            cur = g;
            float deg   = (float)(g_start[g + 1] - g_start[g]);
            float denom = deg + 1e-12f;
            float mean = 0.f;
            if (active) mean = g_sum[g][t] / denom;
            if (t < NSCAL)
                sred[t] = g_sumsq[g][t] / denom - mean * mean;
            __syncthreads();
            if (t == 0) {
                float s = 0.f;
                #pragma unroll 8
                for (int i = 0; i < NSCAL; ++i) s += sred[i];
                snorm = s * (1.0f / NSCAL);
            }
            __syncthreads();
            float inv = 1.0f / (sqrtf(snorm) + EPSV);
            if (active) {
                if (t < NSCAL) { a = w * inv; b = bi - mean * a; }
                else           { a = w;      b = -mean * w;      }
            }
        }
        if (active) {
            int off = r * NTOT + t;
            float v = fmaf(__ldcs(&x[off]), a, b);   // last-use read
            __stcs(&out[off], v);                    // evict-first write
        }
    }
}

extern "C" void kernel_launch(void* const* d_in, const int* in_sizes, int n_in,
                              void* d_out, int out_size) {
    const float* x      = (const float*)d_in[0];
    const float* weight = (const float*)d_in[1];
    const float* bias   = (const float*)d_in[2];
    const void*  batch  = d_in[3];
    int N = in_sizes[0] / NTOT;

    int prep_elems = N > NB * NTOT ? N : NB * NTOT;
    prep_kernel<<<(prep_elems + 255) / 256, 256>>>(batch, N);
    bounds_kernel<<<1, 128>>>(N);

    for (int p = 0; p < NGROUPS; ++p) {
        stats_kernel<<<GRID_MAIN, THREADS>>>(x, p);
        norm_kernel<<<GRID_MAIN, THREADS>>>(x, weight, bias, (float*)d_out, p);
    }
}

// round 2
// speedup vs baseline: 1.7924x; 1.7924x over previous
#include <cuda_runtime.h>

// e3LayerNorm: segment (graph) layernorm over irreps 128x0e + 64x1o + 32x2e.
// out[i,c] = a[g,c]*x[i,c] + b[g,c], a/b fold mean-subtract, inv-std (scalar
// cols), weight, bias. batch is sorted -> graphs contiguous.
//
// Schedule: 8 groups of 8 graphs; alternating stats/norm launches so norm's
// read of the group hits L2 (48MB/group << 126MB L2). Each CTA is pinned to
// ONE graph -> no per-row graph lookup; norm coefficients live in registers.
// Thread layout: 480 threads = 120 float4 columns x 4 row lanes.

#define NTOT    480
#define NC4     120          // float4 columns per row
#define NSCAL   128
#define NB      64
#define GSZ     8
#define NGROUPS (NB / GSZ)
#define CPG     72           // CTAs per graph -> grid 576 (~1 wave @ 4 CTA/SM)
#define THREADS 480
#define EPSV    1e-5f

__device__ int   g_start[NB + 1];
__device__ float g_sum[NB][NTOT];
__device__ float g_sumsq[NB][NSCAL];

// Zero the accumulators (runs every replay; captured in the graph).
__global__ void prep_kernel() {
    int i = blockIdx.x * blockDim.x + threadIdx.x;
    if (i < NB * NTOT)  ((float*)g_sum)[i]   = 0.f;
    if (i < NB * NSCAL) ((float*)g_sumsq)[i] = 0.f;
}

// g_start[g] = lower_bound(batch, g); g_start[NB] = N. Detects int64 vs int32
// batch by probing an odd int32 word near the end (int64 high word == 0).
__global__ void bounds_kernel(const void* __restrict__ batch_raw, int N) {
    int t = threadIdx.x;
    if (t > NB) return;
    const int* b32 = (const int*)batch_raw;
    const long long* b64 = (const long long*)batch_raw;
    int probe = (N & 1) ? (N - 2) : (N - 1);
    bool is64 = (b32[probe] < 32);
    int lo = 0, hi = N;
    while (lo < hi) {
        int mid = (lo + hi) >> 1;
        long long v = is64 ? b64[mid] : (long long)b32[mid];
        if (v < (long long)t) lo = mid + 1; else hi = mid;
    }
    g_start[t] = lo;
}

// Stats: CTA pinned to one graph. Pure float4 streaming accumulate,
// shared reduce across the 4 row-lanes, one atomic flush per column.
__global__ __launch_bounds__(THREADS) void stats_kernel(
    const float4* __restrict__ x4, int group)
{
    __shared__ float4 s_s[4][NC4];
    __shared__ float4 s_q[4][32];

    int t = threadIdx.x;
    int lc = t % NC4;            // float4 column
    int lr = t / NC4;            // row lane 0..3
    int G  = group * GSZ + blockIdx.x / CPG;
    int sub = blockIdx.x % CPG;
    int gs0 = g_start[G], gs1 = g_start[G + 1];
    long long len = (long long)(gs1 - gs0);
    int r0 = gs0 + (int)(len * sub / CPG);
    int r1 = gs0 + (int)(len * (sub + 1) / CPG);

    float4 a0 = {0,0,0,0}, a1 = {0,0,0,0};
    float4 q0 = {0,0,0,0}, q1 = {0,0,0,0};
    bool sc = (lc < 32);

    int r = r0 + lr;
    for (; r + 4 < r1; r += 8) {
        float4 v0 = x4[r * NC4 + lc];
        float4 v1 = x4[(r + 4) * NC4 + lc];
        a0.x += v0.x; a0.y += v0.y; a0.z += v0.z; a0.w += v0.w;
        a1.x += v1.x; a1.y += v1.y; a1.z += v1.z; a1.w += v1.w;
        if (sc) {
            q0.x = fmaf(v0.x, v0.x, q0.x); q0.y = fmaf(v0.y, v0.y, q0.y);
            q0.z = fmaf(v0.z, v0.z, q0.z); q0.w = fmaf(v0.w, v0.w, q0.w);
            q1.x = fmaf(v1.x, v1.x, q1.x); q1.y = fmaf(v1.y, v1.y, q1.y);
            q1.z = fmaf(v1.z, v1.z, q1.z); q1.w = fmaf(v1.w, v1.w, q1.w);
        }
    }
    if (r < r1) {
        float4 v0 = x4[r * NC4 + lc];
        a0.x += v0.x; a0.y += v0.y; a0.z += v0.z; a0.w += v0.w;
        if (sc) {
            q0.x = fmaf(v0.x, v0.x, q0.x); q0.y = fmaf(v0.y, v0.y, q0.y);
            q0.z = fmaf(v0.z, v0.z, q0.z); q0.w = fmaf(v0.w, v0.w, q0.w);
        }
    }
    a0.x += a1.x; a0.y += a1.y; a0.z += a1.z; a0.w += a1.w;
    q0.x += q1.x; q0.y += q1.y; q0.z += q1.z; q0.w += q1.w;

    s_s[lr][lc] = a0;
    if (sc) s_q[lr][lc] = q0;
    __syncthreads();
    if (lr == 0) {
        float4 t0 = s_s[0][lc], t1 = s_s[1][lc], t2 = s_s[2][lc], t3 = s_s[3][lc];
        atomicAdd(&g_sum[G][lc*4+0], t0.x + t1.x + t2.x + t3.x);
        atomicAdd(&g_sum[G][lc*4+1], t0.y + t1.y + t2.y + t3.y);
        atomicAdd(&g_sum[G][lc*4+2], t0.z + t1.z + t2.z + t3.z);
        atomicAdd(&g_sum[G][lc*4+3], t0.w + t1.w + t2.w + t3.w);
        if (sc) {
            float4 u0 = s_q[0][lc], u1 = s_q[1][lc], u2 = s_q[2][lc], u3 = s_q[3][lc];
            atomicAdd(&g_sumsq[G][lc*4+0], u0.x + u1.x + u2.x + u3.x);
            atomicAdd(&g_sumsq[G][lc*4+1], u0.y + u1.y + u2.y + u3.y);
            atomicAdd(&g_sumsq[G][lc*4+2], u0.z + u1.z + u2.z + u3.z);
            atomicAdd(&g_sumsq[G][lc*4+3], u0.w + u1.w + u2.w + u3.w);
        }
    }
}

__device__ __forceinline__ int ch_of(int c) {
    return (c < NSCAL) ? c : (c < 320 ? 128 + (c - 128) / 3
                                      : 192 + (c - 320) / 5);
}

// Norm: CTA pinned to one graph. Prologue computes per-thread register a4/b4
// (warp-0 shuffle reduce for scalar variance). Main loop: LDG.128/FFMA/STG.128.
__global__ __launch_bounds__(THREADS) void norm_kernel(
    const float4* __restrict__ x4,
    const float* __restrict__ weight,
    const float* __restrict__ bias,
    float4* __restrict__ o4, int group)
{
    __shared__ float s_norm;

    int t = threadIdx.x;
    int lc = t % NC4;
    int lr = t / NC4;
    int G  = group * GSZ + blockIdx.x / CPG;
    int sub = blockIdx.x % CPG;
    int gs0 = g_start[G], gs1 = g_start[G + 1];
    long long len = (long long)(gs1 - gs0);
    int r0 = gs0 + (int)(len * sub / CPG);
    int r1 = gs0 + (int)(len * (sub + 1) / CPG);

    float denom = (float)(gs1 - gs0) + 1e-12f;
    float inv_d = 1.0f / denom;

    const float4* gsum4 = (const float4*)g_sum[G];
    float4 s4 = gsum4[lc];
    float4 mean4;
    mean4.x = s4.x * inv_d; mean4.y = s4.y * inv_d;
    mean4.z = s4.z * inv_d; mean4.w = s4.w * inv_d;

    // scalar variance reduce: threads 0..31 (lc==t, lr==0) own sumsq cols
    if (t < 32) {
        const float4* gsq4 = (const float4*)g_sumsq[G];
        float4 q = gsq4[t];
        float v = (q.x * inv_d - mean4.x * mean4.x)
                + (q.y * inv_d - mean4.y * mean4.y)
                + (q.z * inv_d - mean4.z * mean4.z)
                + (q.w * inv_d - mean4.w * mean4.w);
        #pragma unroll
        for (int off = 16; off > 0; off >>= 1)
            v += __shfl_xor_sync(0xffffffffu, v, off);
        if (t == 0) s_norm = v * (1.0f / NSCAL);
    }
    __syncthreads();
    float inv = 1.0f / (sqrtf(s_norm) + EPSV);

    float4 a4, b4;
    {
        float* mp = (float*)&mean4;
        float* ap = (float*)&a4;
        float* bp = (float*)&b4;
        #pragma unroll
        for (int k = 0; k < 4; ++k) {
            int c = lc * 4 + k;
            float w = weight[ch_of(c)];
            if (c < NSCAL) { ap[k] = w * inv; bp[k] = bias[c] - mp[k] * ap[k]; }
            else           { ap[k] = w;       bp[k] = -mp[k] * w; }
        }
    }

    int r = r0 + lr;
    for (; r + 4 < r1; r += 8) {
        int i0 = r * NC4 + lc;
        int i1 = (r + 4) * NC4 + lc;
        float4 v0 = __ldcs(&x4[i0]);
        float4 v1 = __ldcs(&x4[i1]);
        float4 o0, o1;
        o0.x = fmaf(v0.x, a4.x, b4.x); o0.y = fmaf(v0.y, a4.y, b4.y);
        o0.z = fmaf(v0.z, a4.z, b4.z); o0.w = fmaf(v0.w, a4.w, b4.w);
        o1.x = fmaf(v1.x, a4.x, b4.x); o1.y = fmaf(v1.y, a4.y, b4.y);
        o1.z = fmaf(v1.z, a4.z, b4.z); o1.w = fmaf(v1.w, a4.w, b4.w);
        __stcs(&o4[i0], o0);
        __stcs(&o4[i1], o1);
    }
    if (r < r1) {
        int i0 = r * NC4 + lc;
        float4 v0 = __ldcs(&x4[i0]);
        float4 o0;
        o0.x = fmaf(v0.x, a4.x, b4.x); o0.y = fmaf(v0.y, a4.y, b4.y);
        o0.z = fmaf(v0.z, a4.z, b4.z); o0.w = fmaf(v0.w, a4.w, b4.w);
        __stcs(&o4[i0], o0);
    }
}

extern "C" void kernel_launch(void* const* d_in, const int* in_sizes, int n_in,
                              void* d_out, int out_size) {
    const float4* x4    = (const float4*)d_in[0];
    const float* weight = (const float*)d_in[1];
    const float* bias   = (const float*)d_in[2];
    const void*  batch  = d_in[3];
    int N = in_sizes[0] / NTOT;

    prep_kernel<<<(NB * NTOT + 255) / 256, 256>>>();
    bounds_kernel<<<1, 128>>>(batch, N);

    for (int p = 0; p < NGROUPS; ++p) {
        stats_kernel<<<GSZ * CPG, THREADS>>>(x4, p);
        norm_kernel<<<GSZ * CPG, THREADS>>>(x4, weight, bias, (float4*)d_out, p);
    }
}

// round 3
// speedup vs baseline: 2.0332x; 1.1343x over previous
#include <cuda_runtime.h>

// e3LayerNorm over irreps 128x0e+64x1o+32x2e, graph-segmented (batch sorted).
// out[i,c] = a[g,c]*x[i,c] + b[g,c]; a/b fold mean-subtract, inv-std (scalar
// cols), weight, bias.
//
// Schedule: 8 groups of 8 contiguous graphs. Fused launches: in launch k,
// CTAs [0,216) normalize group k-1 (reads hit L2 from previous launch's
// stats, writes stream to DRAM) while CTAs [216,432) compute stats of group k
// (DRAM reads, warming L2). DRAM read+write overlap; 11 launches total.
// Thread layout: 480 threads = 120 float4 columns x 4 row lanes; norm
// coefficients live in registers (CTA pinned to one graph).

#define NTOT     480
#define NC4      120
#define NSCAL    128
#define NB       64
#define GSZ      8
#define NGROUPS  (NB / GSZ)
#define THREADS  480
#define GRID_FUSED 432          // one wave at 3 CTAs/SM (444 slots on 148 SMs)
#define NORM_CTAS  216          // dual-role split: 27 CTAs per graph each
#define EPSV     1e-5f

__device__ int   g_start[NB + 1];
__device__ float g_sum[NB][NTOT];
__device__ float g_sumsq[NB][NSCAL];

__global__ void prep_kernel() {
    int i = blockIdx.x * blockDim.x + threadIdx.x;
    if (i < NB * NTOT)  ((float*)g_sum)[i]   = 0.f;
    if (i < NB * NSCAL) ((float*)g_sumsq)[i] = 0.f;
}

// g_start[g] = lower_bound(batch, g); handles int64 or int32 batch (probe an
// odd int32 word near the end: int64 high word == 0, int32 value ~63).
__global__ void bounds_kernel(const void* __restrict__ batch_raw, int N) {
    int t = threadIdx.x;
    if (t > NB) return;
    const int* b32 = (const int*)batch_raw;
    const long long* b64 = (const long long*)batch_raw;
    int probe = (N & 1) ? (N - 2) : (N - 1);
    bool is64 = (b32[probe] < 32);
    int lo = 0, hi = N;
    while (lo < hi) {
        int mid = (lo + hi) >> 1;
        long long v = is64 ? b64[mid] : (long long)b32[mid];
        if (v < (long long)t) lo = mid + 1; else hi = mid;
    }
    g_start[t] = lo;
}

__device__ __forceinline__ void slice(int G, int sub, int cpg, int& r0, int& r1) {
    int gs0 = g_start[G], gs1 = g_start[G + 1];
    long long len = (long long)(gs1 - gs0);
    r0 = gs0 + (int)(len * sub / cpg);
    r1 = gs0 + (int)(len * (sub + 1) / cpg);
}

__device__ __forceinline__ void acc4(float4& a, float4& q, const float4 v, bool sc) {
    a.x += v.x; a.y += v.y; a.z += v.z; a.w += v.w;
    if (sc) {
        q.x = fmaf(v.x, v.x, q.x); q.y = fmaf(v.y, v.y, q.y);
        q.z = fmaf(v.z, v.z, q.z); q.w = fmaf(v.w, v.w, q.w);
    }
}

__device__ void do_stats(const float4* __restrict__ x4, int group, int idx, int cpg) {
    __shared__ float4 s_s[4][NC4];
    __shared__ float4 s_q[4][32];

    int t = threadIdx.x, lc = t % NC4, lr = t / NC4;
    int G = group * GSZ + idx / cpg;
    int r0, r1; slice(G, idx % cpg, cpg, r0, r1);

    float4 a0 = {0,0,0,0}, a1 = {0,0,0,0};
    float4 q0 = {0,0,0,0}, q1 = {0,0,0,0};
    bool sc = (lc < 32);

    int r = r0 + lr;
    for (; r + 12 < r1; r += 16) {
        int i0 = r * NC4 + lc;
        float4 v0 = x4[i0];
        float4 v1 = x4[i0 + 4 * NC4];
        float4 v2 = x4[i0 + 8 * NC4];
        float4 v3 = x4[i0 + 12 * NC4];
        acc4(a0, q0, v0, sc); acc4(a1, q1, v1, sc);
        acc4(a0, q0, v2, sc); acc4(a1, q1, v3, sc);
    }
    for (; r < r1; r += 4)
        acc4(a0, q0, x4[r * NC4 + lc], sc);

    a0.x += a1.x; a0.y += a1.y; a0.z += a1.z; a0.w += a1.w;
    q0.x += q1.x; q0.y += q1.y; q0.z += q1.z; q0.w += q1.w;

    s_s[lr][lc] = a0;
    if (sc) s_q[lr][lc] = q0;
    __syncthreads();
    if (lr == 0) {
        float4 t0 = s_s[0][lc], t1 = s_s[1][lc], t2 = s_s[2][lc], t3 = s_s[3][lc];
        atomicAdd(&g_sum[G][lc*4+0], t0.x + t1.x + t2.x + t3.x);
        atomicAdd(&g_sum[G][lc*4+1], t0.y + t1.y + t2.y + t3.y);
        atomicAdd(&g_sum[G][lc*4+2], t0.z + t1.z + t2.z + t3.z);
        atomicAdd(&g_sum[G][lc*4+3], t0.w + t1.w + t2.w + t3.w);
        if (sc) {
            float4 u0 = s_q[0][lc], u1 = s_q[1][lc], u2 = s_q[2][lc], u3 = s_q[3][lc];
            atomicAdd(&g_sumsq[G][lc*4+0], u0.x + u1.x + u2.x + u3.x);
            atomicAdd(&g_sumsq[G][lc*4+1], u0.y + u1.y + u2.y + u3.y);
            atomicAdd(&g_sumsq[G][lc*4+2], u0.z + u1.z + u2.z + u3.z);
            atomicAdd(&g_sumsq[G][lc*4+3], u0.w + u1.w + u2.w + u3.w);
        }
    }
}

__device__ __forceinline__ int ch_of(int c) {
    return (c < NSCAL) ? c : (c < 320 ? 128 + (c - 128) / 3
                                      : 192 + (c - 320) / 5);
}

__device__ __forceinline__ float4 fma4(const float4 v, const float4 a, const float4 b) {
    float4 o;
    o.x = fmaf(v.x, a.x, b.x); o.y = fmaf(v.y, a.y, b.y);
    o.z = fmaf(v.z, a.z, b.z); o.w = fmaf(v.w, a.w, b.w);
    return o;
}

__device__ void do_norm(const float4* __restrict__ x4,
                        const float* __restrict__ weight,
                        const float* __restrict__ bias,
                        float4* __restrict__ o4, int group, int idx, int cpg) {
    __shared__ float s_norm;

    int t = threadIdx.x, lc = t % NC4, lr = t / NC4;
    int G = group * GSZ + idx / cpg;
    int r0, r1; slice(G, idx % cpg, cpg, r0, r1);

    float inv_d = 1.0f / ((float)(g_start[G + 1] - g_start[G]) + 1e-12f);

    const float4* gsum4 = (const float4*)g_sum[G];
    float4 s4 = gsum4[lc];
    float4 mean4;
    mean4.x = s4.x * inv_d; mean4.y = s4.y * inv_d;
    mean4.z = s4.z * inv_d; mean4.w = s4.w * inv_d;

    if (t < 32) {
        const float4* gsq4 = (const float4*)g_sumsq[G];
        float4 q = gsq4[t];
        float v = (q.x * inv_d - mean4.x * mean4.x)
                + (q.y * inv_d - mean4.y * mean4.y)
                + (q.z * inv_d - mean4.z * mean4.z)
                + (q.w * inv_d - mean4.w * mean4.w);
        #pragma unroll
        for (int off = 16; off > 0; off >>= 1)
            v += __shfl_xor_sync(0xffffffffu, v, off);
        if (t == 0) s_norm = v * (1.0f / NSCAL);
    }
    __syncthreads();
    float inv = 1.0f / (sqrtf(s_norm) + EPSV);

    float4 a4, b4;
    {
        float* mp = (float*)&mean4;
        float* ap = (float*)&a4;
        float* bp = (float*)&b4;
        #pragma unroll
        for (int k = 0; k < 4; ++k) {
            int c = lc * 4 + k;
            float w = weight[ch_of(c)];
            if (c < NSCAL) { ap[k] = w * inv; bp[k] = bias[c] - mp[k] * ap[k]; }
            else           { ap[k] = w;       bp[k] = -mp[k] * w; }
        }
    }

    int r = r0 + lr;
    for (; r + 12 < r1; r += 16) {
        int i0 = r * NC4 + lc;
        float4 v0 = __ldcs(&x4[i0]);
        float4 v1 = __ldcs(&x4[i0 + 4 * NC4]);
        float4 v2 = __ldcs(&x4[i0 + 8 * NC4]);
        float4 v3 = __ldcs(&x4[i0 + 12 * NC4]);
        __stcs(&o4[i0],            fma4(v0, a4, b4));
        __stcs(&o4[i0 + 4 * NC4],  fma4(v1, a4, b4));
        __stcs(&o4[i0 + 8 * NC4],  fma4(v2, a4, b4));
        __stcs(&o4[i0 + 12 * NC4], fma4(v3, a4, b4));
    }
    for (; r < r1; r += 4) {
        int i0 = r * NC4 + lc;
        __stcs(&o4[i0], fma4(__ldcs(&x4[i0]), a4, b4));
    }
}

// Dual-role fused kernel: blocks [0,nNorm) normalize normGroup, the rest
// compute stats of statsGroup. Either group may be -1 (role absent).
__global__ __launch_bounds__(THREADS) void fused_kernel(
    const float4* __restrict__ x4,
    const float* __restrict__ weight,
    const float* __restrict__ bias,
    float4* __restrict__ o4,
    int normGroup, int statsGroup)
{
    bool haveNorm = (normGroup >= 0), haveStats = (statsGroup >= 0);
    int nNorm = haveNorm ? (haveStats ? NORM_CTAS : GRID_FUSED) : 0;
    if ((int)blockIdx.x < nNorm) {
        do_norm(x4, weight, bias, o4, normGroup, blockIdx.x, nNorm / GSZ);
    } else if (haveStats) {
        int idx = blockIdx.x - nNorm;
        do_stats(x4, statsGroup, idx, (GRID_FUSED - nNorm) / GSZ);
    }
}

extern "C" void kernel_launch(void* const* d_in, const int* in_sizes, int n_in,
                              void* d_out, int out_size) {
    const float4* x4    = (const float4*)d_in[0];
    const float* weight = (const float*)d_in[1];
    const float* bias   = (const float*)d_in[2];
    const void*  batch  = d_in[3];
    int N = in_sizes[0] / NTOT;

    prep_kernel<<<(NB * NTOT + 255) / 256, 256>>>();
    bounds_kernel<<<1, 128>>>(batch, N);

    float4* o4 = (float4*)d_out;
    fused_kernel<<<GRID_FUSED, THREADS>>>(x4, weight, bias, o4, -1, 0);
    for (int p = 0; p < NGROUPS - 1; ++p)
        fused_kernel<<<GRID_FUSED, THREADS>>>(x4, weight, bias, o4, p, p + 1);
    fused_kernel<<<GRID_FUSED, THREADS>>>(x4, weight, bias, o4, NGROUPS - 1, -1);
}